// round 7
// baseline (speedup 1.0000x reference)
#include <cuda_runtime.h>
#include <cstdint>

// Problem constants
#define NB      4096      // nodes per batch (64x64)
#define CDIM    64        // feature channels
#define BATCH   4
#define BR      64        // rows per block (kernel 2)
#define CT      128       // column tile (kernel 2)
#define NTILES  (NB / CT) // 32
#define DSTRIDE 132       // distT row stride (floats), conflict-free for selection

// scratch: per-node squared norm
__device__ float g_sq[BATCH * NB];

// ---------------------------------------------------------------------------
// packed fp32x2 FMA (Blackwell): acc.lo += a.lo*b.lo ; acc.hi += a.hi*b.hi
__device__ __forceinline__ void fma2(unsigned long long &acc,
                                     unsigned long long a,
                                     unsigned long long b) {
    asm("fma.rn.f32x2 %0, %1, %2, %0;" : "+l"(acc) : "l"(a), "l"(b));
}
__device__ __forceinline__ float lo32(unsigned long long v) {
    return __uint_as_float((unsigned)(v & 0xFFFFFFFFull));
}
__device__ __forceinline__ float hi32(unsigned long long v) {
    return __uint_as_float((unsigned)(v >> 32));
}

// sorted ascending top-7 insert; a[6] is current max
__device__ __forceinline__ void insert7(unsigned long long (&a)[7],
                                        unsigned long long key) {
    if (key < a[6]) {
        #pragma unroll
        for (int j = 0; j < 7; j++) {
            unsigned long long lo = key < a[j] ? key : a[j];
            unsigned long long hi = key < a[j] ? a[j] : key;
            a[j] = lo;
            key  = hi;
        }
    }
}

// ---------------------------------------------------------------------------
// Kernel 1: conv 3x3 stride 2 pad 1 -> y[b][n][c] (N,C layout) + per-node sq
__global__ void conv_head(const float* __restrict__ x,
                          const float* __restrict__ wk,
                          const float* __restrict__ bias,
                          float* __restrict__ y) {
    __shared__ float ws[64 * 27];
    __shared__ float wb[64];
    int t = threadIdx.x;
    for (int i = t; i < 64 * 27; i += 256) ws[i] = wk[i];
    if (t < 64) wb[t] = bias[t];
    __syncthreads();

    int gid = blockIdx.x * 256 + t;          // 0..16383 = b*4096 + n
    int b  = gid >> 12;
    int n  = gid & 4095;
    int ho = n >> 6, wo = n & 63;

    float xv[27];
    #pragma unroll
    for (int cin = 0; cin < 3; cin++) {
        #pragma unroll
        for (int kh = 0; kh < 3; kh++) {
            int ih = 2 * ho + kh - 1;
            #pragma unroll
            for (int kw = 0; kw < 3; kw++) {
                int iw = 2 * wo + kw - 1;
                float v = 0.f;
                if (ih >= 0 && ih < 128 && iw >= 0 && iw < 128)
                    v = x[((size_t)(b * 3 + cin) * 128 + ih) * 128 + iw];
                xv[cin * 9 + kh * 3 + kw] = v;
            }
        }
    }

    float s = 0.f;
    float* yrow = y + (size_t)gid * CDIM;
    #pragma unroll 4
    for (int c4 = 0; c4 < 16; c4++) {
        float o[4];
        #pragma unroll
        for (int j = 0; j < 4; j++) {
            int c = c4 * 4 + j;
            float acc = 0.f;
            const float* wc = ws + c * 27;
            #pragma unroll
            for (int i = 0; i < 27; i++) acc = fmaf(xv[i], wc[i], acc);
            acc += wb[c];
            o[j] = acc;
            s = fmaf(acc, acc, s);
        }
        float4 v4 = make_float4(o[0], o[1], o[2], o[3]);
        *(float4*)(yrow + c4 * 4) = v4;
    }
    g_sq[gid] = s;
}

// ---------------------------------------------------------------------------
// Kernel 2: distances + top-7 selection + adjacency write.
// Block: (rowtile, batch). 64 rows x all 4096 cols, streamed in 128-col tiles.
// Dynamic smem layout (floats):
//   rowsD [64][128]  : row features, each value DUPLICATED (for f32x2 b-operand)
//   colsT [64][128]  : column-tile features, k-major
//   colSq [128]      : column sq norms
//   distT [64][132]  : distance tile for the selection pass
// mergeBuf (u64[64][28]) overlays rowsD after the main loop.
__global__ void __launch_bounds__(256, 2)
dist_adj(const float* __restrict__ y, float* __restrict__ adj) {
    extern __shared__ float sm[];
    float* rowsD = sm;                       // 8192 floats
    float* colsT = sm + BR * CT;             // 8192 floats
    float* colSq = colsT + 64 * CT;          // 128 floats
    float* distT = colSq + CT;               // 64*132 floats
    unsigned long long* mrg = (unsigned long long*)sm;  // overlay

    int t = threadIdx.x;
    int b = blockIdx.y;
    int rowbase = blockIdx.x * BR;
    const float* Yb = y + (size_t)b * NB * CDIM;

    // ---- load row tile, duplicated: rowsD[k*128 + 2r] = rowsD[.. + 2r+1]
    {
        int r = t & 63, seg = t >> 6;        // seg in 0..3
        const float4* src = (const float4*)(Yb + (size_t)(rowbase + r) * CDIM);
        #pragma unroll
        for (int i = 0; i < 4; i++) {
            float4 v = src[seg * 4 + i];
            int k0 = seg * 16 + i * 4;
            rowsD[(k0 + 0) * CT + 2 * r] = v.x; rowsD[(k0 + 0) * CT + 2 * r + 1] = v.x;
            rowsD[(k0 + 1) * CT + 2 * r] = v.y; rowsD[(k0 + 1) * CT + 2 * r + 1] = v.y;
            rowsD[(k0 + 2) * CT + 2 * r] = v.z; rowsD[(k0 + 2) * CT + 2 * r + 1] = v.z;
            rowsD[(k0 + 3) * CT + 2 * r] = v.w; rowsD[(k0 + 3) * CT + 2 * r + 1] = v.w;
        }
    }

    // compute-phase mapping: 16 thread-rows x 16 thread-cols
    int tr = t >> 4, tc = t & 15;
    int r0 = tr * 4;          // 4 rows per thread
    int c0 = tc * 8;          // 8 cols per thread (4 f32x2 pairs)
    float rsq[4];
    #pragma unroll
    for (int i = 0; i < 4; i++) rsq[i] = g_sq[b * NB + rowbase + r0 + i];

    // selection-phase mapping: 4 threads per row
    int selRow = t >> 2, selSub = t & 3;
    unsigned long long top[7];
    #pragma unroll
    for (int j = 0; j < 7; j++) top[j] = ~0ull;

    for (int tile = 0; tile < NTILES; tile++) {
        int colbase = tile * CT;
        __syncthreads();   // prior selection readers done with distT/colsT

        // ---- load column tile (k-major, conflict-free STS)
        {
            int c = t & 127, half = t >> 7;
            const float4* src = (const float4*)(Yb + (size_t)(colbase + c) * CDIM);
            #pragma unroll
            for (int i = 0; i < 8; i++) {
                float4 v = src[half * 8 + i];
                int k0 = half * 32 + i * 4;
                colsT[(k0 + 0) * CT + c] = v.x;
                colsT[(k0 + 1) * CT + c] = v.y;
                colsT[(k0 + 2) * CT + c] = v.z;
                colsT[(k0 + 3) * CT + c] = v.w;
            }
            if (t < CT) colSq[t] = g_sq[b * NB + colbase + t];
        }
        __syncthreads();

        // ---- gram: 4 rows x 4 col-pairs of f32x2 accumulators
        unsigned long long acc[4][4];
        #pragma unroll
        for (int i = 0; i < 4; i++)
            #pragma unroll
            for (int p = 0; p < 4; p++) acc[i][p] = 0ull;

        #pragma unroll 16
        for (int k = 0; k < CDIM; k++) {
            const ulonglong2* rp = (const ulonglong2*)&rowsD[k * CT + 2 * r0];
            ulonglong2 rA = rp[0];   // dup(r0), dup(r0+1)
            ulonglong2 rB = rp[1];   // dup(r0+2), dup(r0+3)
            const ulonglong2* cp = (const ulonglong2*)&colsT[k * CT + c0];
            ulonglong2 cA = cp[0];   // pairs (c0,c0+1), (c0+2,c0+3)
            ulonglong2 cB = cp[1];   // pairs (c0+4,c0+5), (c0+6,c0+7)
            fma2(acc[0][0], cA.x, rA.x); fma2(acc[0][1], cA.y, rA.x);
            fma2(acc[0][2], cB.x, rA.x); fma2(acc[0][3], cB.y, rA.x);
            fma2(acc[1][0], cA.x, rA.y); fma2(acc[1][1], cA.y, rA.y);
            fma2(acc[1][2], cB.x, rA.y); fma2(acc[1][3], cB.y, rA.y);
            fma2(acc[2][0], cA.x, rB.x); fma2(acc[2][1], cA.y, rB.x);
            fma2(acc[2][2], cB.x, rB.x); fma2(acc[2][3], cB.y, rB.x);
            fma2(acc[3][0], cA.x, rB.y); fma2(acc[3][1], cA.y, rB.y);
            fma2(acc[3][2], cB.x, rB.y); fma2(acc[3][3], cB.y, rB.y);
        }

        // ---- epilogue: d = sqrt(max((sq_n + sq_m) - 2*g, 0))
        #pragma unroll
        for (int i = 0; i < 4; i++) {
            int rr = r0 + i;
            float sn = rsq[i];
            #pragma unroll
            for (int p = 0; p < 4; p++) {
                int cc = c0 + 2 * p;
                float g0 = lo32(acc[i][p]);
                float g1 = hi32(acc[i][p]);
                float d0 = (sn + colSq[cc])     - 2.0f * g0;
                float d1 = (sn + colSq[cc + 1]) - 2.0f * g1;
                distT[rr * DSTRIDE + cc]     = __fsqrt_rn(fmaxf(d0, 0.0f));
                distT[rr * DSTRIDE + cc + 1] = __fsqrt_rn(fmaxf(d1, 0.0f));
            }
        }
        __syncthreads();

        // ---- selection: running top-7 keys (dist_bits, index) per row
        #pragma unroll 4
        for (int q = 0; q < 32; q++) {
            int ml = selSub + 4 * q;                      // conflict-free banks
            float d = distT[selRow * DSTRIDE + ml];
            unsigned long long key =
                ((unsigned long long)__float_as_uint(d) << 32) |
                (unsigned)(colbase + ml);
            insert7(top, key);
        }
    }
    __syncthreads();

    // ---- dump candidates (overlay on rowsD; compute phase is done)
    #pragma unroll
    for (int j = 0; j < 7; j++)
        mrg[selRow * 28 + selSub * 7 + j] = top[j];
    __syncthreads();

    // ---- zero-fill this block's 64 adjacency rows
    float4 z = make_float4(0.f, 0.f, 0.f, 0.f);
    for (int rr = 0; rr < BR; rr++) {
        float4* dst = (float4*)(adj + ((size_t)b * NB + rowbase + rr) * NB);
        #pragma unroll 4
        for (int j = t; j < NB / 4; j += 256) dst[j] = z;
    }
    __syncthreads();

    // ---- final merge (28 -> 7) + scatter ones
    if (t < BR) {
        unsigned long long fin[7];
        #pragma unroll
        for (int j = 0; j < 7; j++) fin[j] = ~0ull;
        for (int s = 0; s < 28; s++) insert7(fin, mrg[t * 28 + s]);
        float* dst = adj + ((size_t)b * NB + rowbase + t) * NB;
        #pragma unroll
        for (int j = 0; j < 7; j++)
            dst[(unsigned)(fin[j] & 0xFFFFFFFFull)] = 1.0f;
    }
}

// ---------------------------------------------------------------------------
extern "C" void kernel_launch(void* const* d_in, const int* in_sizes, int n_in,
                              void* d_out, int out_size) {
    const float* x    = (const float*)d_in[0];   // [4,3,128,128]
    const float* wk   = (const float*)d_in[1];   // [64,3,3,3]
    const float* bias = (const float*)d_in[2];   // [64]
    float* out = (float*)d_out;
    float* y   = out;                                    // [4,4096,64]
    float* adj = out + (size_t)BATCH * NB * CDIM;        // [4,4096,4096]

    conv_head<<<BATCH * NB / 256, 256>>>(x, wk, bias, y);

    const int smem = (BR * CT + 64 * CT + CT + BR * DSTRIDE) * (int)sizeof(float);
    cudaFuncSetAttribute(dist_adj, cudaFuncAttributeMaxDynamicSharedMemorySize, smem);
    dist_adj<<<dim3(NB / BR, BATCH), 256, smem>>>(y, adj);
}

// round 15
// speedup vs baseline: 1.2498x; 1.2498x over previous
#include <cuda_runtime.h>
#include <cstdint>

// Problem constants
#define NB      4096      // nodes per batch (64x64)
#define CDIM    64        // feature channels
#define BATCH   4
#define BR      64        // rows per block (kernel 2)
#define CT      128       // column tile (kernel 2)
#define NTILES  (NB / CT) // 32
#define DSTRIDE 130       // distT row stride: conflict-free selection + 2-phase STS.64

typedef unsigned long long u64;

// scratch: per-node squared norm
__device__ float g_sq[BATCH * NB];

// ---------------------------------------------------------------------------
// packed fp32x2 FMA (Blackwell): acc.lo += a.lo*b.lo ; acc.hi += a.hi*b.hi
__device__ __forceinline__ void fma2(u64 &acc, u64 a, u64 b) {
    asm("fma.rn.f32x2 %0, %1, %2, %0;" : "+l"(acc) : "l"(a), "l"(b));
}
__device__ __forceinline__ u64 dup2(float x) {            // {x, x}
    u64 r; asm("mov.b64 %0, {%1, %1};" : "=l"(r) : "f"(x)); return r;
}
__device__ __forceinline__ u64 pack2(float lo, float hi) {
    u64 r; asm("mov.b64 %0, {%1, %2};" : "=l"(r) : "f"(lo), "f"(hi)); return r;
}
__device__ __forceinline__ float lo32(u64 v) {
    return __uint_as_float((unsigned)(v & 0xFFFFFFFFull));
}
__device__ __forceinline__ float hi32(u64 v) {
    return __uint_as_float((unsigned)(v >> 32));
}

// sorted ascending top-7 insert; a[6] is current max
__device__ __forceinline__ void insert7(u64 (&a)[7], u64 key) {
    if (key < a[6]) {
        #pragma unroll
        for (int j = 0; j < 7; j++) {
            u64 lo = key < a[j] ? key : a[j];
            u64 hi = key < a[j] ? a[j] : key;
            a[j] = lo;
            key  = hi;
        }
    }
}

// ---------------------------------------------------------------------------
// Kernel 1: conv 3x3 stride 2 pad 1 -> y[b][n][c] (N,C layout) + per-node sq
__global__ void conv_head(const float* __restrict__ x,
                          const float* __restrict__ wk,
                          const float* __restrict__ bias,
                          float* __restrict__ y) {
    __shared__ float ws[64 * 27];
    __shared__ float wb[64];
    int t = threadIdx.x;
    for (int i = t; i < 64 * 27; i += 256) ws[i] = wk[i];
    if (t < 64) wb[t] = bias[t];
    __syncthreads();

    int gid = blockIdx.x * 256 + t;          // 0..16383 = b*4096 + n
    int b  = gid >> 12;
    int n  = gid & 4095;
    int ho = n >> 6, wo = n & 63;

    float xv[27];
    #pragma unroll
    for (int cin = 0; cin < 3; cin++) {
        #pragma unroll
        for (int kh = 0; kh < 3; kh++) {
            int ih = 2 * ho + kh - 1;
            #pragma unroll
            for (int kw = 0; kw < 3; kw++) {
                int iw = 2 * wo + kw - 1;
                float v = 0.f;
                if (ih >= 0 && ih < 128 && iw >= 0 && iw < 128)
                    v = x[((size_t)(b * 3 + cin) * 128 + ih) * 128 + iw];
                xv[cin * 9 + kh * 3 + kw] = v;
            }
        }
    }

    float s = 0.f;
    float* yrow = y + (size_t)gid * CDIM;
    #pragma unroll 4
    for (int c4 = 0; c4 < 16; c4++) {
        float o[4];
        #pragma unroll
        for (int j = 0; j < 4; j++) {
            int c = c4 * 4 + j;
            float acc = 0.f;
            const float* wc = ws + c * 27;
            #pragma unroll
            for (int i = 0; i < 27; i++) acc = fmaf(xv[i], wc[i], acc);
            acc += wb[c];
            o[j] = acc;
            s = fmaf(acc, acc, s);
        }
        float4 v4 = make_float4(o[0], o[1], o[2], o[3]);
        *(float4*)(yrow + c4 * 4) = v4;
    }
    g_sq[gid] = s;
}

// ---------------------------------------------------------------------------
// Kernel 2 (v2): 8x8 per-thread tile, rows de-duplicated in smem (register
// dup), register prefetch of next column tile. 128 threads, 2 CTAs/SM.
// smem (floats): rowsS[64][64] @0, colsP[64][128] @4096, colSq[128] @12288,
//                distT[64][130] @12416.  Total 20736 floats = 82,944 B.
// mrg (u64[64][14]) overlays rowsS after the main loop.
__global__ void __launch_bounds__(128, 2)
dist_adj(const float* __restrict__ y, float* __restrict__ adj) {
    extern __shared__ float sm[];
    float* rowsS = sm;               // 4096 floats
    float* colsP = sm + 4096;        // 8192 floats
    float* colSq = sm + 12288;       // 128 floats
    float* distT = sm + 12416;       // 8320 floats
    u64*   mrg   = (u64*)sm;         // overlay on rowsS

    int t = threadIdx.x;
    int b = blockIdx.y;
    int rowbase = blockIdx.x * BR;
    const float* Yb = y + (size_t)b * NB * CDIM;

    // ---- zero-fill this block's 64 adjacency rows early (drain overlaps)
    {
        float4 z = make_float4(0.f, 0.f, 0.f, 0.f);
        float4* base = (float4*)(adj + ((size_t)b * NB + rowbase) * NB);
        #pragma unroll 4
        for (int j = t; j < BR * NB / 4; j += 128) base[j] = z;
    }

    // ---- load row tile to smem, k-major scalar: rowsS[k][r]
    {
        int r = t & 63, half = t >> 6;
        const float4* src = (const float4*)(Yb + (size_t)(rowbase + r) * CDIM) + half * 8;
        #pragma unroll
        for (int i = 0; i < 8; i++) {
            float4 v = src[i];
            int k0 = half * 32 + i * 4;
            rowsS[(k0 + 0) * 64 + r] = v.x;
            rowsS[(k0 + 1) * 64 + r] = v.y;
            rowsS[(k0 + 2) * 64 + r] = v.z;
            rowsS[(k0 + 3) * 64 + r] = v.w;
        }
    }

    // compute mapping: 8 thread-rows x 16 thread-cols; 8 rows x 8 cols each.
    // cols as 4 spread f32x2 pairs: cc(p) = 2*tc + 32*p (+0/1)
    int tr = t >> 4, tc = t & 15;
    int r0 = tr * 8;
    int cbase = 2 * tc;
    float rsq[8];
    #pragma unroll
    for (int i = 0; i < 8; i++) rsq[i] = g_sq[b * NB + rowbase + r0 + i];

    // ---- preload column tile 0 (1 thread : 1 column)
    float4 pf[16];
    float  pfs;
    {
        const float4* src = (const float4*)(Yb + (size_t)t * CDIM);
        #pragma unroll
        for (int i = 0; i < 16; i++) pf[i] = src[i];
        pfs = g_sq[b * NB + t];
    }
    #pragma unroll
    for (int i = 0; i < 16; i++) {
        float4 v = pf[i]; int k0 = i * 4;
        colsP[(k0 + 0) * CT + t] = v.x;
        colsP[(k0 + 1) * CT + t] = v.y;
        colsP[(k0 + 2) * CT + t] = v.z;
        colsP[(k0 + 3) * CT + t] = v.w;
    }
    colSq[t] = pfs;

    // selection mapping: 2 threads per row, interleaved columns
    int selRow = t >> 1, selSub = t & 1;
    u64 top[7];
    #pragma unroll
    for (int j = 0; j < 7; j++) top[j] = ~0ull;

    for (int tile = 0; tile < NTILES; tile++) {
        __syncthreads();   // colsP/colSq(tile) visible; distT readers done
        int colbase = tile * CT;

        // prefetch next column tile into registers (hidden behind gram)
        if (tile + 1 < NTILES) {
            const float4* src = (const float4*)(Yb + (size_t)(colbase + CT + t) * CDIM);
            #pragma unroll
            for (int i = 0; i < 16; i++) pf[i] = src[i];
            pfs = g_sq[b * NB + colbase + CT + t];
        }

        // ---- gram: 8 rows x 4 col-pairs (32 f32x2 accumulators)
        u64 acc[32];
        #pragma unroll
        for (int i = 0; i < 32; i++) acc[i] = 0ull;

        #pragma unroll 8
        for (int k = 0; k < CDIM; k++) {
            float4 ra = *(const float4*)&rowsS[k * 64 + r0];
            float4 rb = *(const float4*)&rowsS[k * 64 + r0 + 4];
            u64 dA0 = dup2(ra.x), dA1 = dup2(ra.y), dA2 = dup2(ra.z), dA3 = dup2(ra.w);
            u64 dB0 = dup2(rb.x), dB1 = dup2(rb.y), dB2 = dup2(rb.z), dB3 = dup2(rb.w);
            const float* ck = &colsP[k * CT + cbase];
            u64 c0 = *(const u64*)(ck);
            u64 c1 = *(const u64*)(ck + 32);
            u64 c2 = *(const u64*)(ck + 64);
            u64 c3 = *(const u64*)(ck + 96);
            fma2(acc[ 0], c0, dA0); fma2(acc[ 1], c1, dA0); fma2(acc[ 2], c2, dA0); fma2(acc[ 3], c3, dA0);
            fma2(acc[ 4], c0, dA1); fma2(acc[ 5], c1, dA1); fma2(acc[ 6], c2, dA1); fma2(acc[ 7], c3, dA1);
            fma2(acc[ 8], c0, dA2); fma2(acc[ 9], c1, dA2); fma2(acc[10], c2, dA2); fma2(acc[11], c3, dA2);
            fma2(acc[12], c0, dA3); fma2(acc[13], c1, dA3); fma2(acc[14], c2, dA3); fma2(acc[15], c3, dA3);
            fma2(acc[16], c0, dB0); fma2(acc[17], c1, dB0); fma2(acc[18], c2, dB0); fma2(acc[19], c3, dB0);
            fma2(acc[20], c0, dB1); fma2(acc[21], c1, dB1); fma2(acc[22], c2, dB1); fma2(acc[23], c3, dB1);
            fma2(acc[24], c0, dB2); fma2(acc[25], c1, dB2); fma2(acc[26], c2, dB2); fma2(acc[27], c3, dB2);
            fma2(acc[28], c0, dB3); fma2(acc[29], c1, dB3); fma2(acc[30], c2, dB3); fma2(acc[31], c3, dB3);
        }

        // ---- epilogue: d = sqrt(max((sq_n + sq_m) - 2*g, 0)) -> distT
        float csq[8];
        #pragma unroll
        for (int p = 0; p < 4; p++) {
            csq[2 * p]     = colSq[cbase + 32 * p];
            csq[2 * p + 1] = colSq[cbase + 32 * p + 1];
        }
        #pragma unroll
        for (int i = 0; i < 8; i++) {
            float sn = rsq[i];
            #pragma unroll
            for (int p = 0; p < 4; p++) {
                float g0 = lo32(acc[i * 4 + p]);
                float g1 = hi32(acc[i * 4 + p]);
                float d0 = (sn + csq[2 * p])     - 2.0f * g0;
                float d1 = (sn + csq[2 * p + 1]) - 2.0f * g1;
                float s0 = __fsqrt_rn(fmaxf(d0, 0.0f));
                float s1 = __fsqrt_rn(fmaxf(d1, 0.0f));
                *(u64*)&distT[(r0 + i) * DSTRIDE + cbase + 32 * p] = pack2(s0, s1);
            }
        }
        __syncthreads();   // distT ready; all gram reads of colsP complete

        // ---- store prefetched next tile into colsP (disjoint from distT)
        if (tile + 1 < NTILES) {
            #pragma unroll
            for (int i = 0; i < 16; i++) {
                float4 v = pf[i]; int k0 = i * 4;
                colsP[(k0 + 0) * CT + t] = v.x;
                colsP[(k0 + 1) * CT + t] = v.y;
                colsP[(k0 + 2) * CT + t] = v.z;
                colsP[(k0 + 3) * CT + t] = v.w;
            }
            colSq[t] = pfs;
        }

        // ---- selection: running top-7 keys (sqrt_bits, index) per row
        #pragma unroll 4
        for (int q = 0; q < 64; q++) {
            int ml = selSub + 2 * q;                  // conflict-free banks
            float d = distT[selRow * DSTRIDE + ml];
            u64 key = ((u64)__float_as_uint(d) << 32) | (unsigned)(colbase + ml);
            insert7(top, key);
        }
    }
    __syncthreads();

    // ---- dump candidates (overlay on rowsS; gram phase is done)
    #pragma unroll
    for (int j = 0; j < 7; j++)
        mrg[selRow * 14 + selSub * 7 + j] = top[j];
    __syncthreads();

    // ---- final merge (14 -> 7) + scatter ones
    if (t < BR) {
        u64 fin[7];
        #pragma unroll
        for (int j = 0; j < 7; j++) fin[j] = ~0ull;
        #pragma unroll
        for (int s = 0; s < 14; s++) insert7(fin, mrg[t * 14 + s]);
        float* dst = adj + ((size_t)b * NB + rowbase + t) * NB;
        #pragma unroll
        for (int j = 0; j < 7; j++)
            dst[(unsigned)(fin[j] & 0xFFFFFFFFull)] = 1.0f;
    }
}

// ---------------------------------------------------------------------------
extern "C" void kernel_launch(void* const* d_in, const int* in_sizes, int n_in,
                              void* d_out, int out_size) {
    const float* x    = (const float*)d_in[0];   // [4,3,128,128]
    const float* wk   = (const float*)d_in[1];   // [64,3,3,3]
    const float* bias = (const float*)d_in[2];   // [64]
    float* out = (float*)d_out;
    float* y   = out;                                    // [4,4096,64]
    float* adj = out + (size_t)BATCH * NB * CDIM;        // [4,4096,4096]

    conv_head<<<BATCH * NB / 256, 256>>>(x, wk, bias, y);

    const int smem = (64 * 64 + 64 * CT + CT + BR * DSTRIDE) * (int)sizeof(float);
    cudaFuncSetAttribute(dist_adj, cudaFuncAttributeMaxDynamicSharedMemorySize, smem);
    dist_adj<<<dim3(NB / BR, BATCH), 128, smem>>>(y, adj);
}

// round 16
// speedup vs baseline: 1.3205x; 1.0566x over previous
#include <cuda_runtime.h>
#include <cstdint>

// Problem constants
#define NB      4096      // nodes per batch (64x64)
#define CDIM    64        // feature channels
#define BATCH   4
#define BR      64        // rows per block (kernel 2)
#define CT      128       // column tile (kernel 2)
#define NTILES  (NB / CT) // 32
#define DSTRIDE 130       // distT row stride: conflict-free selection + 2-phase STS.64

typedef unsigned long long u64;

// scratch: per-node squared norm
__device__ float g_sq[BATCH * NB];

// ---------------------------------------------------------------------------
// packed fp32x2 FMA (Blackwell): acc.lo += a.lo*b.lo ; acc.hi += a.hi*b.hi
__device__ __forceinline__ void fma2(u64 &acc, u64 a, u64 b) {
    asm("fma.rn.f32x2 %0, %1, %2, %0;" : "+l"(acc) : "l"(a), "l"(b));
}
__device__ __forceinline__ u64 dup2(float x) {            // {x, x}
    u64 r; asm("mov.b64 %0, {%1, %1};" : "=l"(r) : "f"(x)); return r;
}
__device__ __forceinline__ u64 pack2(float lo, float hi) {
    u64 r; asm("mov.b64 %0, {%1, %2};" : "=l"(r) : "f"(lo), "f"(hi)); return r;
}
__device__ __forceinline__ float lo32(u64 v) {
    return __uint_as_float((unsigned)(v & 0xFFFFFFFFull));
}
__device__ __forceinline__ float hi32(u64 v) {
    return __uint_as_float((unsigned)(v >> 32));
}

// sorted ascending top-7 insert; a[6] is current max
__device__ __forceinline__ void insert7(u64 (&a)[7], u64 key) {
    if (key < a[6]) {
        #pragma unroll
        for (int j = 0; j < 7; j++) {
            u64 lo = key < a[j] ? key : a[j];
            u64 hi = key < a[j] ? a[j] : key;
            a[j] = lo;
            key  = hi;
        }
    }
}

// ---------------------------------------------------------------------------
// Kernel 1: conv 3x3 stride 2 pad 1 -> y[b][n][c] (N,C layout) + per-node sq
__global__ void conv_head(const float* __restrict__ x,
                          const float* __restrict__ wk,
                          const float* __restrict__ bias,
                          float* __restrict__ y) {
    __shared__ float ws[64 * 27];
    __shared__ float wb[64];
    int t = threadIdx.x;
    for (int i = t; i < 64 * 27; i += 256) ws[i] = wk[i];
    if (t < 64) wb[t] = bias[t];
    __syncthreads();

    int gid = blockIdx.x * 256 + t;          // 0..16383 = b*4096 + n
    int b  = gid >> 12;
    int n  = gid & 4095;
    int ho = n >> 6, wo = n & 63;

    float xv[27];
    #pragma unroll
    for (int cin = 0; cin < 3; cin++) {
        #pragma unroll
        for (int kh = 0; kh < 3; kh++) {
            int ih = 2 * ho + kh - 1;
            #pragma unroll
            for (int kw = 0; kw < 3; kw++) {
                int iw = 2 * wo + kw - 1;
                float v = 0.f;
                if (ih >= 0 && ih < 128 && iw >= 0 && iw < 128)
                    v = x[((size_t)(b * 3 + cin) * 128 + ih) * 128 + iw];
                xv[cin * 9 + kh * 3 + kw] = v;
            }
        }
    }

    float s = 0.f;
    float* yrow = y + (size_t)gid * CDIM;
    #pragma unroll 4
    for (int c4 = 0; c4 < 16; c4++) {
        float o[4];
        #pragma unroll
        for (int j = 0; j < 4; j++) {
            int c = c4 * 4 + j;
            float acc = 0.f;
            const float* wc = ws + c * 27;
            #pragma unroll
            for (int i = 0; i < 27; i++) acc = fmaf(xv[i], wc[i], acc);
            acc += wb[c];
            o[j] = acc;
            s = fmaf(acc, acc, s);
        }
        float4 v4 = make_float4(o[0], o[1], o[2], o[3]);
        *(float4*)(yrow + c4 * 4) = v4;
    }
    g_sq[gid] = s;
}

// gram inner step (one k) — 8 rows x 4 col-pairs of f32x2 accumulators
#define GRAM_K(k)                                                             \
    {                                                                         \
        float4 ra = *(const float4*)&rowsS[(k) * 64 + r0];                    \
        float4 rb = *(const float4*)&rowsS[(k) * 64 + r0 + 4];                \
        u64 dA0 = dup2(ra.x), dA1 = dup2(ra.y), dA2 = dup2(ra.z), dA3 = dup2(ra.w); \
        u64 dB0 = dup2(rb.x), dB1 = dup2(rb.y), dB2 = dup2(rb.z), dB3 = dup2(rb.w); \
        const float* ck = &colsP[(k) * CT + cbase];                           \
        u64 c0 = *(const u64*)(ck);                                           \
        u64 c1 = *(const u64*)(ck + 32);                                      \
        u64 c2 = *(const u64*)(ck + 64);                                      \
        u64 c3 = *(const u64*)(ck + 96);                                      \
        fma2(acc[ 0], c0, dA0); fma2(acc[ 1], c1, dA0); fma2(acc[ 2], c2, dA0); fma2(acc[ 3], c3, dA0); \
        fma2(acc[ 4], c0, dA1); fma2(acc[ 5], c1, dA1); fma2(acc[ 6], c2, dA1); fma2(acc[ 7], c3, dA1); \
        fma2(acc[ 8], c0, dA2); fma2(acc[ 9], c1, dA2); fma2(acc[10], c2, dA2); fma2(acc[11], c3, dA2); \
        fma2(acc[12], c0, dA3); fma2(acc[13], c1, dA3); fma2(acc[14], c2, dA3); fma2(acc[15], c3, dA3); \
        fma2(acc[16], c0, dB0); fma2(acc[17], c1, dB0); fma2(acc[18], c2, dB0); fma2(acc[19], c3, dB0); \
        fma2(acc[20], c0, dB1); fma2(acc[21], c1, dB1); fma2(acc[22], c2, dB1); fma2(acc[23], c3, dB1); \
        fma2(acc[24], c0, dB2); fma2(acc[25], c1, dB2); fma2(acc[26], c2, dB2); fma2(acc[27], c3, dB2); \
        fma2(acc[28], c0, dB3); fma2(acc[29], c1, dB3); fma2(acc[30], c2, dB3); fma2(acc[31], c3, dB3); \
    }

// one selection step q for the tile whose columns start at cb
#define SEL_Q(q, cb)                                                          \
    {                                                                         \
        int ml = selSub + 2 * (q);                                            \
        float d = distT[selRow * DSTRIDE + ml];                               \
        u64 key = ((u64)__float_as_uint(d) << 32) | (unsigned)((cb) + ml);    \
        insert7(top, key);                                                    \
    }

// ---------------------------------------------------------------------------
// Kernel 2 (v3): v2 + selection(t-1) fused into gram(t) so the serial
// selection phase hides in gram stall slots. Same barriers, same arithmetic.
// smem (floats): rowsS[64][64] @0, colsP[64][128] @4096, colSq[128] @12288,
//                distT[64][130] @12416.  Total 20736 floats = 82,944 B.
// mrg (u64[64][14]) overlays rowsS after the main loop.
__global__ void __launch_bounds__(128, 2)
dist_adj(const float* __restrict__ y, float* __restrict__ adj) {
    extern __shared__ float sm[];
    float* rowsS = sm;               // 4096 floats
    float* colsP = sm + 4096;        // 8192 floats
    float* colSq = sm + 12288;       // 128 floats
    float* distT = sm + 12416;       // 8320 floats
    u64*   mrg   = (u64*)sm;         // overlay on rowsS

    int t = threadIdx.x;
    int b = blockIdx.y;
    int rowbase = blockIdx.x * BR;
    const float* Yb = y + (size_t)b * NB * CDIM;

    // ---- zero-fill this block's 64 adjacency rows early (drain overlaps)
    {
        float4 z = make_float4(0.f, 0.f, 0.f, 0.f);
        float4* base = (float4*)(adj + ((size_t)b * NB + rowbase) * NB);
        #pragma unroll 4
        for (int j = t; j < BR * NB / 4; j += 128) base[j] = z;
    }

    // ---- load row tile to smem, k-major scalar: rowsS[k][r]
    {
        int r = t & 63, half = t >> 6;
        const float4* src = (const float4*)(Yb + (size_t)(rowbase + r) * CDIM) + half * 8;
        #pragma unroll
        for (int i = 0; i < 8; i++) {
            float4 v = src[i];
            int k0 = half * 32 + i * 4;
            rowsS[(k0 + 0) * 64 + r] = v.x;
            rowsS[(k0 + 1) * 64 + r] = v.y;
            rowsS[(k0 + 2) * 64 + r] = v.z;
            rowsS[(k0 + 3) * 64 + r] = v.w;
        }
    }

    // compute mapping: 8 thread-rows x 16 thread-cols; 8 rows x 8 cols each.
    int tr = t >> 4, tc = t & 15;
    int r0 = tr * 8;
    int cbase = 2 * tc;
    float rsq[8];
    #pragma unroll
    for (int i = 0; i < 8; i++) rsq[i] = g_sq[b * NB + rowbase + r0 + i];

    // ---- preload column tile 0 (1 thread : 1 column)
    float4 pf[16];
    float  pfs;
    {
        const float4* src = (const float4*)(Yb + (size_t)t * CDIM);
        #pragma unroll
        for (int i = 0; i < 16; i++) pf[i] = src[i];
        pfs = g_sq[b * NB + t];
    }
    #pragma unroll
    for (int i = 0; i < 16; i++) {
        float4 v = pf[i]; int k0 = i * 4;
        colsP[(k0 + 0) * CT + t] = v.x;
        colsP[(k0 + 1) * CT + t] = v.y;
        colsP[(k0 + 2) * CT + t] = v.z;
        colsP[(k0 + 3) * CT + t] = v.w;
    }
    colSq[t] = pfs;

    // selection mapping: 2 threads per row, interleaved columns
    int selRow = t >> 1, selSub = t & 1;
    u64 top[7];
    #pragma unroll
    for (int j = 0; j < 7; j++) top[j] = ~0ull;

    for (int tile = 0; tile < NTILES; tile++) {
        __syncthreads();   // syncA: colsP/colSq(tile) ready; distT(tile-1) written
        int colbase = tile * CT;

        // prefetch next column tile into registers (hidden behind gram)
        if (tile + 1 < NTILES) {
            const float4* src = (const float4*)(Yb + (size_t)(colbase + CT + t) * CDIM);
            #pragma unroll
            for (int i = 0; i < 16; i++) pf[i] = src[i];
            pfs = g_sq[b * NB + colbase + CT + t];
        }

        u64 acc[32];
        #pragma unroll
        for (int i = 0; i < 32; i++) acc[i] = 0ull;

        if (tile == 0) {
            // ---- gram only (no previous tile to select from)
            #pragma unroll 8
            for (int k = 0; k < CDIM; k++) GRAM_K(k);
        } else {
            // ---- gram(tile) fused with selection(tile-1): sel LDS/ALU ops
            //      fill gram stall slots; fma pipe stays busy.
            int cbp = colbase - CT;
            #pragma unroll 8
            for (int k = 0; k < CDIM; k++) {
                GRAM_K(k);
                SEL_Q(k, cbp);
            }
        }

        // ---- epilogue: d = sqrt(max((sq_n + sq_m) - 2*g, 0)) -> distT
        float csq[8];
        #pragma unroll
        for (int p = 0; p < 4; p++) {
            csq[2 * p]     = colSq[cbase + 32 * p];
            csq[2 * p + 1] = colSq[cbase + 32 * p + 1];
        }
        __syncthreads();   // syncB: gram reads of colsP done; sel reads of distT done
        #pragma unroll
        for (int i = 0; i < 8; i++) {
            float sn = rsq[i];
            #pragma unroll
            for (int p = 0; p < 4; p++) {
                float g0 = lo32(acc[i * 4 + p]);
                float g1 = hi32(acc[i * 4 + p]);
                float d0 = (sn + csq[2 * p])     - 2.0f * g0;
                float d1 = (sn + csq[2 * p + 1]) - 2.0f * g1;
                float s0 = __fsqrt_rn(fmaxf(d0, 0.0f));
                float s1 = __fsqrt_rn(fmaxf(d1, 0.0f));
                *(u64*)&distT[(r0 + i) * DSTRIDE + cbase + 32 * p] = pack2(s0, s1);
            }
        }

        // ---- store prefetched next tile into colsP (disjoint from distT)
        if (tile + 1 < NTILES) {
            #pragma unroll
            for (int i = 0; i < 16; i++) {
                float4 v = pf[i]; int k0 = i * 4;
                colsP[(k0 + 0) * CT + t] = v.x;
                colsP[(k0 + 1) * CT + t] = v.y;
                colsP[(k0 + 2) * CT + t] = v.z;
                colsP[(k0 + 3) * CT + t] = v.w;
            }
            colSq[t] = pfs;
        }
    }
    __syncthreads();       // epi(NTILES-1) writes to distT visible

    // ---- trailing selection for the last tile
    {
        int cbp = (NTILES - 1) * CT;
        #pragma unroll 8
        for (int q = 0; q < 64; q++) SEL_Q(q, cbp);
    }
    __syncthreads();

    // ---- dump candidates (overlay on rowsS; gram phase is done)
    #pragma unroll
    for (int j = 0; j < 7; j++)
        mrg[selRow * 14 + selSub * 7 + j] = top[j];
    __syncthreads();

    // ---- final merge (14 -> 7) + scatter ones
    if (t < BR) {
        u64 fin[7];
        #pragma unroll
        for (int j = 0; j < 7; j++) fin[j] = ~0ull;
        #pragma unroll
        for (int s = 0; s < 14; s++) insert7(fin, mrg[t * 14 + s]);
        float* dst = adj + ((size_t)b * NB + rowbase + t) * NB;
        #pragma unroll
        for (int j = 0; j < 7; j++)
            dst[(unsigned)(fin[j] & 0xFFFFFFFFull)] = 1.0f;
    }
}

// ---------------------------------------------------------------------------
extern "C" void kernel_launch(void* const* d_in, const int* in_sizes, int n_in,
                              void* d_out, int out_size) {
    const float* x    = (const float*)d_in[0];   // [4,3,128,128]
    const float* wk   = (const float*)d_in[1];   // [64,3,3,3]
    const float* bias = (const float*)d_in[2];   // [64]
    float* out = (float*)d_out;
    float* y   = out;                                    // [4,4096,64]
    float* adj = out + (size_t)BATCH * NB * CDIM;        // [4,4096,4096]

    conv_head<<<BATCH * NB / 256, 256>>>(x, wk, bias, y);

    const int smem = (64 * 64 + 64 * CT + CT + BR * DSTRIDE) * (int)sizeof(float);
    cudaFuncSetAttribute(dist_adj, cudaFuncAttributeMaxDynamicSharedMemorySize, smem);
    dist_adj<<<dim3(NB / BR, BATCH), 128, smem>>>(y, adj);
}